// round 2
// baseline (speedup 1.0000x reference)
#include <cuda_runtime.h>
#include <math.h>

#define B_  4
#define S_  2048
#define DM  768
#define H_  12
#define DK  64
#define BH  (B_*H_)

// Scratch: QKV projections. K stored transposed per (b,h): [bh][d][s].
__device__ float g_Q[BH * S_ * DK];
__device__ float g_K[BH * DK * S_];
__device__ float g_V[BH * S_ * DK];

// ---------------------------------------------------------------------------
// Projection GEMM: C[M=8192, N=768] = X @ W + bias, scattered to head layout.
// Block tile 64x64, 256 threads, each computes 4x4. K-step 16.
// WHICH: 0 -> g_Q ([bh][s][d]), 1 -> g_K ([bh][d][s]), 2 -> g_V ([bh][s][d])
// ---------------------------------------------------------------------------
template<int WHICH>
__global__ void __launch_bounds__(256) proj_kernel(const float* __restrict__ X,
                                                   const float* __restrict__ W,
                                                   const float* __restrict__ bias)
{
    __shared__ float As[64][17];   // [m][kk], padded
    __shared__ float Ws[16][64];   // [kk][n]

    const int tid = threadIdx.x;
    const int tx = tid & 15, ty = tid >> 4;
    const int m0 = blockIdx.y * 64;
    const int n0 = blockIdx.x * 64;
    const int row = ty * 4, col = tx * 4;

    float acc[4][4] = {};

    for (int k0 = 0; k0 < DM; k0 += 16) {
        #pragma unroll
        for (int j = 0; j < 4; j++) {
            int r = (tid >> 4) + j * 16;
            As[r][tid & 15] = X[(m0 + r) * DM + k0 + (tid & 15)];
        }
        #pragma unroll
        for (int j = 0; j < 4; j++) {
            int kk = (tid >> 6) + j * 4;
            Ws[kk][tid & 63] = W[(k0 + kk) * DM + n0 + (tid & 63)];
        }
        __syncthreads();

        #pragma unroll
        for (int kk = 0; kk < 16; kk++) {
            float a0 = As[row + 0][kk];
            float a1 = As[row + 1][kk];
            float a2 = As[row + 2][kk];
            float a3 = As[row + 3][kk];
            float4 w = *(const float4*)&Ws[kk][col];
            acc[0][0] += a0 * w.x; acc[0][1] += a0 * w.y; acc[0][2] += a0 * w.z; acc[0][3] += a0 * w.w;
            acc[1][0] += a1 * w.x; acc[1][1] += a1 * w.y; acc[1][2] += a1 * w.z; acc[1][3] += a1 * w.w;
            acc[2][0] += a2 * w.x; acc[2][1] += a2 * w.y; acc[2][2] += a2 * w.z; acc[2][3] += a2 * w.w;
            acc[3][0] += a3 * w.x; acc[3][1] += a3 * w.y; acc[3][2] += a3 * w.z; acc[3][3] += a3 * w.w;
        }
        __syncthreads();
    }

    float* out = (WHICH == 0) ? g_Q : (WHICH == 1) ? g_K : g_V;
    const int h = n0 >> 6;             // 64-wide n-tiles align exactly with heads
    #pragma unroll
    for (int c = 0; c < 4; c++) {
        float bb = bias[n0 + col + c];
        #pragma unroll
        for (int r = 0; r < 4; r++) {
            int m = m0 + row + r;
            int b = m >> 11;           // m / 2048
            int s = m & 2047;
            int bh = b * H_ + h;
            float v = acc[r][c] + bb;
            if (WHICH == 1)
                out[(bh * DK + (col + c)) * S_ + s] = v;   // K transposed
            else
                out[(bh * S_ + s) * DK + (col + c)] = v;
        }
    }
}

// ---------------------------------------------------------------------------
// Flash attention: one block = one (b,h) x 64 queries. KV tiles of 32 keys.
// 128 threads:
//   scores 64x32 -> thread tile 4x4 (ty 0..15 -> q, tx 0..7 -> k)
//   output 64x64 -> thread tile 4x8
// ---------------------------------------------------------------------------
__global__ void __launch_bounds__(128) attn_kernel(float* __restrict__ out)
{
    __shared__ float Qs[64][65];   // [q][d]
    __shared__ float Ks[64][36];   // [d][key]  pad 36 -> float4-aligned rows
    __shared__ float Vs[32][68];   // [key][d]  pad 68 -> float4-aligned rows
    __shared__ float Ps[64][36];   // [q][key]

    const int tid = threadIdx.x;
    const int tx = tid & 7, ty = tid >> 3;
    const int row  = ty * 4;       // query rows (4)
    const int colK = tx * 4;       // score cols (4)
    const int colD = tx * 8;       // output dims (8)
    const int q0 = blockIdx.x * 64;
    const int bh = blockIdx.y;

    // Load Q tile 64x64 (coalesced, 32 elems/thread)
    #pragma unroll
    for (int j = 0; j < 32; j++) {
        int r = (tid >> 6) + j * 2;
        int d = tid & 63;
        Qs[r][d] = g_Q[(bh * S_ + q0 + r) * DK + d];
    }

    float mrow[4], lrow[4], O[4][8];
    #pragma unroll
    for (int r = 0; r < 4; r++) {
        mrow[r] = -1e30f; lrow[r] = 0.f;
        #pragma unroll
        for (int c = 0; c < 8; c++) O[r][c] = 0.f;
    }

    const float scale = 0.125f;   // 1/sqrt(64)

    for (int k0 = 0; k0 < S_; k0 += 32) {
        __syncthreads();   // previous iteration's smem reads complete
        // K tile: Ks[d][key]; g_K is [bh][d][s] -> coalesced along s
        #pragma unroll
        for (int j = 0; j < 16; j++) {
            int d  = (tid >> 5) + j * 4;
            int ky = tid & 31;
            Ks[d][ky] = g_K[(bh * DK + d) * S_ + k0 + ky];
        }
        // V tile: Vs[key][d]
        #pragma unroll
        for (int j = 0; j < 16; j++) {
            int ky = (tid >> 6) + j * 2;
            int d  = tid & 63;
            Vs[ky][d] = g_V[(bh * S_ + k0 + ky) * DK + d];
        }
        __syncthreads();

        // S = Q K^T : thread 4x4, 16 FMA per 5 LDS issues
        float s[4][4] = {};
        #pragma unroll 8
        for (int d = 0; d < 64; d++) {
            float q0_ = Qs[row + 0][d];
            float q1_ = Qs[row + 1][d];
            float q2_ = Qs[row + 2][d];
            float q3_ = Qs[row + 3][d];
            float4 kv = *(const float4*)&Ks[d][colK];
            s[0][0] += q0_ * kv.x; s[0][1] += q0_ * kv.y; s[0][2] += q0_ * kv.z; s[0][3] += q0_ * kv.w;
            s[1][0] += q1_ * kv.x; s[1][1] += q1_ * kv.y; s[1][2] += q1_ * kv.z; s[1][3] += q1_ * kv.w;
            s[2][0] += q2_ * kv.x; s[2][1] += q2_ * kv.y; s[2][2] += q2_ * kv.z; s[2][3] += q2_ * kv.w;
            s[3][0] += q3_ * kv.x; s[3][1] += q3_ * kv.y; s[3][2] += q3_ * kv.z; s[3][3] += q3_ * kv.w;
        }

        // Online softmax over the 32-key tile (8 tx lanes x 4 cols per row)
        #pragma unroll
        for (int r = 0; r < 4; r++) {
            float mx = fmaxf(fmaxf(s[r][0], s[r][1]), fmaxf(s[r][2], s[r][3])) * scale;
            #pragma unroll
            for (int off = 4; off; off >>= 1)
                mx = fmaxf(mx, __shfl_xor_sync(0xffffffffu, mx, off));
            float mnew = fmaxf(mrow[r], mx);
            float p0 = __expf(s[r][0] * scale - mnew);
            float p1 = __expf(s[r][1] * scale - mnew);
            float p2 = __expf(s[r][2] * scale - mnew);
            float p3 = __expf(s[r][3] * scale - mnew);
            float sum = (p0 + p1) + (p2 + p3);
            #pragma unroll
            for (int off = 4; off; off >>= 1)
                sum += __shfl_xor_sync(0xffffffffu, sum, off);
            float alpha = __expf(mrow[r] - mnew);
            lrow[r] = lrow[r] * alpha + sum;
            mrow[r] = mnew;
            #pragma unroll
            for (int c = 0; c < 8; c++) O[r][c] *= alpha;
            float4 pv = make_float4(p0, p1, p2, p3);
            *(float4*)&Ps[row + r][colK] = pv;
        }
        __syncthreads();

        // O += P @ V : thread 4x8, 32 FMA per 6 LDS issues
        #pragma unroll 4
        for (int k = 0; k < 32; k++) {
            float p0 = Ps[row + 0][k];
            float p1 = Ps[row + 1][k];
            float p2 = Ps[row + 2][k];
            float p3 = Ps[row + 3][k];
            float4 va = *(const float4*)&Vs[k][colD];
            float4 vb = *(const float4*)&Vs[k][colD + 4];
            O[0][0] += p0 * va.x; O[0][1] += p0 * va.y; O[0][2] += p0 * va.z; O[0][3] += p0 * va.w;
            O[0][4] += p0 * vb.x; O[0][5] += p0 * vb.y; O[0][6] += p0 * vb.z; O[0][7] += p0 * vb.w;
            O[1][0] += p1 * va.x; O[1][1] += p1 * va.y; O[1][2] += p1 * va.z; O[1][3] += p1 * va.w;
            O[1][4] += p1 * vb.x; O[1][5] += p1 * vb.y; O[1][6] += p1 * vb.z; O[1][7] += p1 * vb.w;
            O[2][0] += p2 * va.x; O[2][1] += p2 * va.y; O[2][2] += p2 * va.z; O[2][3] += p2 * va.w;
            O[2][4] += p2 * vb.x; O[2][5] += p2 * vb.y; O[2][6] += p2 * vb.z; O[2][7] += p2 * vb.w;
            O[3][0] += p3 * va.x; O[3][1] += p3 * va.y; O[3][2] += p3 * va.z; O[3][3] += p3 * va.w;
            O[3][4] += p3 * vb.x; O[3][5] += p3 * vb.y; O[3][6] += p3 * vb.z; O[3][7] += p3 * vb.w;
        }
    }

    // Epilogue: normalize, write to [B, S, H*DK] with float4 stores
    const int b = bh / H_;
    const int h = bh % H_;
    #pragma unroll
    for (int r = 0; r < 4; r++) {
        float inv = 1.0f / lrow[r];
        int s = q0 + row + r;
        float* dst = &out[(b * S_ + s) * DM + h * DK + colD];
        float4 oa = make_float4(O[r][0] * inv, O[r][1] * inv, O[r][2] * inv, O[r][3] * inv);
        float4 ob = make_float4(O[r][4] * inv, O[r][5] * inv, O[r][6] * inv, O[r][7] * inv);
        *(float4*)&dst[0] = oa;
        *(float4*)&dst[4] = ob;
    }
}

// ---------------------------------------------------------------------------
extern "C" void kernel_launch(void* const* d_in, const int* in_sizes, int n_in,
                              void* d_out, int out_size)
{
    const float* q   = (const float*)d_in[0];
    const float* k   = (const float*)d_in[1];
    const float* v   = (const float*)d_in[2];
    const float* W_Q = (const float*)d_in[3];
    const float* b_Q = (const float*)d_in[4];
    const float* W_K = (const float*)d_in[5];
    const float* b_K = (const float*)d_in[6];
    const float* W_V = (const float*)d_in[7];
    const float* b_V = (const float*)d_in[8];
    float* out = (float*)d_out;

    dim3 pgrid(DM / 64, (B_ * S_) / 64);   // (12, 128)
    proj_kernel<0><<<pgrid, 256>>>(q, W_Q, b_Q);
    proj_kernel<1><<<pgrid, 256>>>(k, W_K, b_K);
    proj_kernel<2><<<pgrid, 256>>>(v, W_V, b_V);

    dim3 agrid(S_ / 64, BH);               // (32, 48)
    attn_kernel<<<agrid, 128>>>(out);
}

// round 4
// speedup vs baseline: 1.6859x; 1.6859x over previous
#include <cuda_runtime.h>
#include <cuda_bf16.h>
#include <math.h>

#define B_  4
#define S_  2048
#define DM  768
#define H_  12
#define DK  64
#define BH  (B_*H_)

// bf16 hi/lo projection outputs. Q,K: [bh][s][64]. V transposed: [bh][d][s].
__device__ __align__(256) __nv_bfloat16 g_Qh[BH * S_ * DK];
__device__ __align__(256) __nv_bfloat16 g_Ql[BH * S_ * DK];
__device__ __align__(256) __nv_bfloat16 g_Kh[BH * S_ * DK];
__device__ __align__(256) __nv_bfloat16 g_Kl[BH * S_ * DK];
__device__ __align__(256) __nv_bfloat16 g_Vh[BH * DK * S_];
__device__ __align__(256) __nv_bfloat16 g_Vl[BH * DK * S_];

// ---------------------------------------------------------------------------
// Helpers (sm_80-era ISA only: ldmatrix + mma.sync -- legal on compute_103)
// ---------------------------------------------------------------------------
__device__ __forceinline__ unsigned smem_u32(const void* p) {
    unsigned a;
    asm("{ .reg .u64 t; cvta.to.shared.u64 t, %1; cvt.u32.u64 %0, t; }" : "=r"(a) : "l"(p));
    return a;
}
__device__ __forceinline__ void ldsm4(unsigned* r, unsigned a) {
    asm volatile("ldmatrix.sync.aligned.m8n8.x4.shared.b16 {%0,%1,%2,%3}, [%4];"
                 : "=r"(r[0]), "=r"(r[1]), "=r"(r[2]), "=r"(r[3]) : "r"(a));
}
__device__ __forceinline__ void mma16816(float* c, const unsigned* a, const unsigned* b) {
    asm volatile("mma.sync.aligned.m16n8k16.row.col.f32.bf16.bf16.f32 "
                 "{%0,%1,%2,%3}, {%4,%5,%6,%7}, {%8,%9}, {%0,%1,%2,%3};"
                 : "+f"(c[0]), "+f"(c[1]), "+f"(c[2]), "+f"(c[3])
                 : "r"(a[0]), "r"(a[1]), "r"(a[2]), "r"(a[3]), "r"(b[0]), "r"(b[1]));
}
// pack two f32 into bf16x2 (lo element -> low half)
__device__ __forceinline__ unsigned packbf(float lo, float hi) {
    unsigned r;
    asm("cvt.rn.bf16x2.f32 %0, %1, %2;" : "=r"(r) : "f"(hi), "f"(lo));
    return r;
}
// 2^t for t <= 0, FMA/ALU pipes only (no MUFU). |rel err| ~ 2e-6.
__device__ __forceinline__ float exp2fast(float t) {
    t = fmaxf(t, -120.f);
    float r = t + 12582912.f;            // 1.5*2^23: round-to-nearest-int
    float f = t - (r - 12582912.f);      // f in [-0.5, 0.5]
    int   i = __float_as_int(r) - 0x4B400000;
    float p = 0.0013333558f;
    p = fmaf(p, f, 0.0096181291f);
    p = fmaf(p, f, 0.0555041087f);
    p = fmaf(p, f, 0.2402265070f);
    p = fmaf(p, f, 0.6931471806f);
    p = fmaf(p, f, 1.0f);
    return p * __int_as_float((i + 127) << 23);
}
#define SWZ(o) ((o) ^ (((o) >> 3) & 0x70))

// ---------------------------------------------------------------------------
// Projection GEMM (fp32 FFMA): C = X @ W + bias -> bf16 hi/lo head layouts.
// WHICH: 0 Q, 1 K (both [bh][s][d]), 2 V (transposed [bh][d][s])
// ---------------------------------------------------------------------------
template<int WHICH>
__global__ void __launch_bounds__(256) proj_kernel(const float* __restrict__ X,
                                                   const float* __restrict__ W,
                                                   const float* __restrict__ bias)
{
    __shared__ float As[64][17];
    __shared__ float Ws[16][64];

    const int tid = threadIdx.x;
    const int tx = tid & 15, ty = tid >> 4;
    const int m0 = blockIdx.y * 64;
    const int n0 = blockIdx.x * 64;
    const int row = ty * 4, col = tx * 4;

    float acc[4][4] = {};

    for (int k0 = 0; k0 < DM; k0 += 16) {
        #pragma unroll
        for (int j = 0; j < 4; j++) {
            int r = (tid >> 4) + j * 16;
            As[r][tid & 15] = X[(m0 + r) * DM + k0 + (tid & 15)];
        }
        #pragma unroll
        for (int j = 0; j < 4; j++) {
            int kk = (tid >> 6) + j * 4;
            Ws[kk][tid & 63] = W[(k0 + kk) * DM + n0 + (tid & 63)];
        }
        __syncthreads();
        #pragma unroll
        for (int kk = 0; kk < 16; kk++) {
            float a0 = As[row + 0][kk], a1 = As[row + 1][kk];
            float a2 = As[row + 2][kk], a3 = As[row + 3][kk];
            float4 w = *(const float4*)&Ws[kk][col];
            acc[0][0] += a0 * w.x; acc[0][1] += a0 * w.y; acc[0][2] += a0 * w.z; acc[0][3] += a0 * w.w;
            acc[1][0] += a1 * w.x; acc[1][1] += a1 * w.y; acc[1][2] += a1 * w.z; acc[1][3] += a1 * w.w;
            acc[2][0] += a2 * w.x; acc[2][1] += a2 * w.y; acc[2][2] += a2 * w.z; acc[2][3] += a2 * w.w;
            acc[3][0] += a3 * w.x; acc[3][1] += a3 * w.y; acc[3][2] += a3 * w.z; acc[3][3] += a3 * w.w;
        }
        __syncthreads();
    }

    __nv_bfloat16 *oh = (WHICH == 0) ? g_Qh : (WHICH == 1) ? g_Kh : g_Vh;
    __nv_bfloat16 *ol = (WHICH == 0) ? g_Ql : (WHICH == 1) ? g_Kl : g_Vl;
    const int h = n0 >> 6;
    #pragma unroll
    for (int c = 0; c < 4; c++) {
        float bb = bias[n0 + col + c];
        #pragma unroll
        for (int r = 0; r < 4; r++) {
            int m = m0 + row + r;
            int b = m >> 11;
            int s = m & 2047;
            int bh = b * H_ + h;
            int d = col + c;
            float v = acc[r][c] + bb;
            __nv_bfloat16 vh = __float2bfloat16(v);
            __nv_bfloat16 vl = __float2bfloat16(v - __bfloat162float(vh));
            long idx = (WHICH == 2) ? ((long)(bh * DK + d) * S_ + s)
                                    : ((long)(bh * S_ + s) * DK + d);
            oh[idx] = vh;
            ol[idx] = vl;
        }
    }
}

// ---------------------------------------------------------------------------
// HMMA flash attention. CTA = 64 queries of one bh; 4 warps, each 16 q-rows.
// Key tiles of 64. Split-bf16 3-term mma for QK^T and PV. exp2 on FMA pipe.
// smem: Q 64x64 hi/lo + K 64x64 hi/lo ([key][d]) + V 64x64 hi/lo ([d][key]).
// ---------------------------------------------------------------------------
#define OQH 0u
#define OQL 8192u
#define OKH 16384u
#define OKL 24576u
#define OVH 32768u
#define OVL 40960u
#define SMEM_BYTES 49152

__global__ void __launch_bounds__(128) attn_mma_kernel(float* __restrict__ out)
{
    extern __shared__ char sm[];
    const unsigned sb = smem_u32(sm);
    const int tid  = threadIdx.x;
    const int lane = tid & 31;
    const int wid  = tid >> 5;
    const int q0 = blockIdx.x * 64;
    const int bh = blockIdx.y;

    // ldmatrix lane address mappings
    const int aRow = lane & 15;                         // A: rows 0..15
    const int aSel = (lane >> 4) & 1;                   // A: +16B for k8..15
    const int bRow = ((lane >> 4) & 1) * 8 + (lane & 7);// B: n rows
    const int bSel = (lane >> 3) & 1;                   // B: +16B for k8..15
    const int qbase = wid * 16;

    // Load Q tile (64x64 hi/lo), swizzled
    {
        const uint4* qh = (const uint4*)g_Qh + (size_t)(bh * S_ + q0) * 8;
        const uint4* ql = (const uint4*)g_Ql + (size_t)(bh * S_ + q0) * 8;
        #pragma unroll
        for (int i = 0; i < 4; i++) {
            int c = tid + i * 128;
            int row = c >> 3, col = c & 7;
            unsigned sw = SWZ((unsigned)(row * 128 + col * 16));
            *(uint4*)(sm + OQH + sw) = qh[row * 8 + col];
            *(uint4*)(sm + OQL + sw) = ql[row * 8 + col];
        }
    }

    float O[8][4];
    #pragma unroll
    for (int i = 0; i < 8; i++)
        #pragma unroll
        for (int j = 0; j < 4; j++) O[i][j] = 0.f;
    float m20 = -1e30f, m21 = -1e30f, l0 = 0.f, l1 = 0.f;
    const float SC = 0.1803368801111333f;   // 0.125 * log2(e)

    for (int k0 = 0; k0 < S_; k0 += 64) {
        __syncthreads();   // prior iteration readers done (iter0: Q stores done)
        // K tile [key][d] hi/lo
        {
            const uint4* kh = (const uint4*)g_Kh + (size_t)(bh * S_ + k0) * 8;
            const uint4* kl = (const uint4*)g_Kl + (size_t)(bh * S_ + k0) * 8;
            #pragma unroll
            for (int i = 0; i < 4; i++) {
                int c = tid + i * 128;
                int row = c >> 3, col = c & 7;
                unsigned sw = SWZ((unsigned)(row * 128 + col * 16));
                *(uint4*)(sm + OKH + sw) = kh[row * 8 + col];
                *(uint4*)(sm + OKL + sw) = kl[row * 8 + col];
            }
            // V tile [d][key] hi/lo (g_V is [bh][d][s])
            const uint4* vh = (const uint4*)g_Vh + (size_t)(bh * DK) * 256 + k0 / 8;
            const uint4* vl = (const uint4*)g_Vl + (size_t)(bh * DK) * 256 + k0 / 8;
            #pragma unroll
            for (int i = 0; i < 4; i++) {
                int c = tid + i * 128;
                int row = c >> 3, col = c & 7;
                unsigned sw = SWZ((unsigned)(row * 128 + col * 16));
                *(uint4*)(sm + OVH + sw) = vh[row * 256 + col];
                *(uint4*)(sm + OVL + sw) = vl[row * 256 + col];
            }
        }
        __syncthreads();

        // ---- S = Q K^T (16q x 64k per warp), split-bf16 3 terms ----
        float S[8][4];
        #pragma unroll
        for (int i = 0; i < 8; i++)
            #pragma unroll
            for (int j = 0; j < 4; j++) S[i][j] = 0.f;

        #pragma unroll
        for (int c = 0; c < 4; c++) {
            unsigned qoff = SWZ((unsigned)((qbase + aRow) * 128 + c * 32 + aSel * 16));
            unsigned qh4[4], ql4[4];
            ldsm4(qh4, sb + OQH + qoff);
            ldsm4(ql4, sb + OQL + qoff);
            #pragma unroll
            for (int t = 0; t < 4; t++) {
                unsigned koff = SWZ((unsigned)((t * 16 + bRow) * 128 + c * 32 + bSel * 16));
                unsigned kh4[4], kl4[4];
                ldsm4(kh4, sb + OKH + koff);
                ldsm4(kl4, sb + OKL + koff);
                mma16816(S[2*t],   qh4, kh4);
                mma16816(S[2*t+1], qh4, kh4 + 2);
                mma16816(S[2*t],   ql4, kh4);
                mma16816(S[2*t+1], ql4, kh4 + 2);
                mma16816(S[2*t],   qh4, kl4);
                mma16816(S[2*t+1], qh4, kl4 + 2);
            }
        }

        // ---- online softmax in log2 domain (rows r = lane>>2, r+8) ----
        float smax0 = -1e30f, smax1 = -1e30f;
        #pragma unroll
        for (int nt = 0; nt < 8; nt++) {
            smax0 = fmaxf(smax0, fmaxf(S[nt][0], S[nt][1]));
            smax1 = fmaxf(smax1, fmaxf(S[nt][2], S[nt][3]));
        }
        smax0 = fmaxf(smax0, __shfl_xor_sync(0xffffffffu, smax0, 1));
        smax0 = fmaxf(smax0, __shfl_xor_sync(0xffffffffu, smax0, 2));
        smax1 = fmaxf(smax1, __shfl_xor_sync(0xffffffffu, smax1, 1));
        smax1 = fmaxf(smax1, __shfl_xor_sync(0xffffffffu, smax1, 2));

        float mn0 = fmaxf(m20, smax0 * SC);
        float mn1 = fmaxf(m21, smax1 * SC);
        float al0 = exp2fast(m20 - mn0);
        float al1 = exp2fast(m21 - mn1);
        m20 = mn0; m21 = mn1;
        #pragma unroll
        for (int nt = 0; nt < 8; nt++) {
            O[nt][0] *= al0; O[nt][1] *= al0;
            O[nt][2] *= al1; O[nt][3] *= al1;
        }

        unsigned ph[4][4], pl[4][4];
        float rs0 = 0.f, rs1 = 0.f;
        #pragma unroll
        for (int t = 0; t < 4; t++) {
            #pragma unroll
            for (int u = 0; u < 2; u++) {
                float* s4 = S[2*t + u];
                float p0 = exp2fast(fmaf(s4[0], SC, -mn0));
                float p1 = exp2fast(fmaf(s4[1], SC, -mn0));
                float p2 = exp2fast(fmaf(s4[2], SC, -mn1));
                float p3 = exp2fast(fmaf(s4[3], SC, -mn1));
                rs0 += p0 + p1;
                rs1 += p2 + p3;
                unsigned h01 = packbf(p0, p1);
                unsigned h23 = packbf(p2, p3);
                float q0f = __int_as_float(h01 << 16);
                float q1f = __int_as_float(h01 & 0xFFFF0000u);
                float q2f = __int_as_float(h23 << 16);
                float q3f = __int_as_float(h23 & 0xFFFF0000u);
                ph[t][u*2]   = h01;
                ph[t][u*2+1] = h23;
                pl[t][u*2]   = packbf(p0 - q0f, p1 - q1f);
                pl[t][u*2+1] = packbf(p2 - q2f, p3 - q3f);
            }
        }
        rs0 += __shfl_xor_sync(0xffffffffu, rs0, 1);
        rs0 += __shfl_xor_sync(0xffffffffu, rs0, 2);
        rs1 += __shfl_xor_sync(0xffffffffu, rs1, 1);
        rs1 += __shfl_xor_sync(0xffffffffu, rs1, 2);
        l0 = l0 * al0 + rs0;
        l1 = l1 * al1 + rs1;

        // ---- O += P V, split-bf16 3 terms ----
        #pragma unroll
        for (int kc = 0; kc < 4; kc++) {
            #pragma unroll
            for (int du = 0; du < 4; du++) {
                unsigned voff = SWZ((unsigned)((du * 16 + bRow) * 128 + kc * 32 + bSel * 16));
                unsigned vh4[4], vl4[4];
                ldsm4(vh4, sb + OVH + voff);
                ldsm4(vl4, sb + OVL + voff);
                mma16816(O[2*du],   ph[kc], vh4);
                mma16816(O[2*du+1], ph[kc], vh4 + 2);
                mma16816(O[2*du],   pl[kc], vh4);
                mma16816(O[2*du+1], pl[kc], vh4 + 2);
                mma16816(O[2*du],   ph[kc], vl4);
                mma16816(O[2*du+1], ph[kc], vl4 + 2);
            }
        }
    }

    // ---- epilogue ----
    {
        float inv0 = 1.0f / l0, inv1 = 1.0f / l1;
        int b = bh / H_, h = bh % H_;
        int r0 = lane >> 2;
        int colb = (lane & 3) * 2;
        float* base0 = out + (size_t)(b * S_ + q0 + qbase + r0) * DM + h * DK;
        float* base1 = base0 + 8 * DM;
        #pragma unroll
        for (int nt = 0; nt < 8; nt++) {
            float2 v0 = make_float2(O[nt][0] * inv0, O[nt][1] * inv0);
            float2 v1 = make_float2(O[nt][2] * inv1, O[nt][3] * inv1);
            *(float2*)(base0 + nt * 8 + colb) = v0;
            *(float2*)(base1 + nt * 8 + colb) = v1;
        }
    }
}

// ---------------------------------------------------------------------------
extern "C" void kernel_launch(void* const* d_in, const int* in_sizes, int n_in,
                              void* d_out, int out_size)
{
    const float* q   = (const float*)d_in[0];
    const float* k   = (const float*)d_in[1];
    const float* v   = (const float*)d_in[2];
    const float* W_Q = (const float*)d_in[3];
    const float* b_Q = (const float*)d_in[4];
    const float* W_K = (const float*)d_in[5];
    const float* b_K = (const float*)d_in[6];
    const float* W_V = (const float*)d_in[7];
    const float* b_V = (const float*)d_in[8];
    float* out = (float*)d_out;

    cudaFuncSetAttribute(attn_mma_kernel, cudaFuncAttributeMaxDynamicSharedMemorySize, SMEM_BYTES);

    dim3 pgrid(DM / 64, (B_ * S_) / 64);   // (12, 128)
    proj_kernel<0><<<pgrid, 256>>>(q, W_Q, b_Q);
    proj_kernel<1><<<pgrid, 256>>>(k, W_K, b_K);
    proj_kernel<2><<<pgrid, 256>>>(v, W_V, b_V);

    dim3 agrid(S_ / 64, BH);               // (32, 48)
    attn_mma_kernel<<<agrid, 128, SMEM_BYTES>>>(out);
}

// round 10
// speedup vs baseline: 2.7337x; 1.6215x over previous
#include <cuda_runtime.h>
#include <cuda_bf16.h>
#include <math.h>

#define B_  4
#define S_  2048
#define DM  768
#define H_  12
#define DK  64
#define BH  (B_*H_)
#define MK  (B_*S_*DM)     // 6291456 elems per input tensor

// bf16 hi/lo inputs (X = query/key/value), slot-indexed
__device__ __align__(256) __nv_bfloat16 g_Xh[3 * MK];
__device__ __align__(256) __nv_bfloat16 g_Xl[3 * MK];
// W^T hi/lo, [n][k] layout, slot-indexed
__device__ __align__(256) __nv_bfloat16 g_WTh[3 * DM * DM];
__device__ __align__(256) __nv_bfloat16 g_WTl[3 * DM * DM];
// projection outputs. Q,K: [bh][s][64]. V transposed: [bh][d][s].
__device__ __align__(256) __nv_bfloat16 g_Qh[BH * S_ * DK];
__device__ __align__(256) __nv_bfloat16 g_Ql[BH * S_ * DK];
__device__ __align__(256) __nv_bfloat16 g_Kh[BH * S_ * DK];
__device__ __align__(256) __nv_bfloat16 g_Kl[BH * S_ * DK];
__device__ __align__(256) __nv_bfloat16 g_Vh[BH * DK * S_];
__device__ __align__(256) __nv_bfloat16 g_Vl[BH * DK * S_];

// ---------------------------------------------------------------------------
// Helpers (sm_80-era ISA only: ldmatrix + mma.sync -- legal on compute_103)
// ---------------------------------------------------------------------------
__device__ __forceinline__ unsigned smem_u32(const void* p) {
    unsigned a;
    asm("{ .reg .u64 t; cvta.to.shared.u64 t, %1; cvt.u32.u64 %0, t; }" : "=r"(a) : "l"(p));
    return a;
}
__device__ __forceinline__ void ldsm4(unsigned* r, unsigned a) {
    asm volatile("ldmatrix.sync.aligned.m8n8.x4.shared.b16 {%0,%1,%2,%3}, [%4];"
                 : "=r"(r[0]), "=r"(r[1]), "=r"(r[2]), "=r"(r[3]) : "r"(a));
}
__device__ __forceinline__ void mma16816(float* c, const unsigned* a, const unsigned* b) {
    asm volatile("mma.sync.aligned.m16n8k16.row.col.f32.bf16.bf16.f32 "
                 "{%0,%1,%2,%3}, {%4,%5,%6,%7}, {%8,%9}, {%0,%1,%2,%3};"
                 : "+f"(c[0]), "+f"(c[1]), "+f"(c[2]), "+f"(c[3])
                 : "r"(a[0]), "r"(a[1]), "r"(a[2]), "r"(a[3]), "r"(b[0]), "r"(b[1]));
}
// pack two f32 into bf16x2 (first arg -> low half)
__device__ __forceinline__ unsigned packbf(float lo, float hi) {
    unsigned r;
    asm("cvt.rn.bf16x2.f32 %0, %1, %2;" : "=r"(r) : "f"(hi), "f"(lo));
    return r;
}
// 2^t, FMA/ALU pipes only. |rel err| ~ 2e-6.
__device__ __forceinline__ float exp2fast(float t) {
    t = fmaxf(t, -120.f);
    float r = t + 12582912.f;
    float f = t - (r - 12582912.f);
    int   i = __float_as_int(r) - 0x4B400000;
    float p = 0.0013333558f;
    p = fmaf(p, f, 0.0096181291f);
    p = fmaf(p, f, 0.0555041087f);
    p = fmaf(p, f, 0.2402265070f);
    p = fmaf(p, f, 0.6931471806f);
    p = fmaf(p, f, 1.0f);
    return p * __int_as_float((i + 127) << 23);
}
#define SWZ(o) ((o) ^ (((o) >> 3) & 0x70))

// ---------------------------------------------------------------------------
// Prepass 1: fp32 -> bf16 hi/lo (vectorized), one launch per input tensor
// ---------------------------------------------------------------------------
__global__ void __launch_bounds__(256) cvt_x_kernel(const float* __restrict__ x, int slot)
{
    int i = blockIdx.x * 256 + threadIdx.x;   // one float4 per thread
    float4 v = ((const float4*)x)[i];
    unsigned h0 = packbf(v.x, v.y);
    unsigned h1 = packbf(v.z, v.w);
    unsigned l0 = packbf(v.x - __int_as_float(h0 << 16), v.y - __int_as_float(h0 & 0xFFFF0000u));
    unsigned l1 = packbf(v.z - __int_as_float(h1 << 16), v.w - __int_as_float(h1 & 0xFFFF0000u));
    ((uint2*)(g_Xh + (size_t)slot * MK))[i] = make_uint2(h0, h1);
    ((uint2*)(g_Xl + (size_t)slot * MK))[i] = make_uint2(l0, l1);
}

// ---------------------------------------------------------------------------
// Prepass 2: W [k][n] fp32 -> W^T [n][k] bf16 hi/lo (32x32 smem transpose)
// ---------------------------------------------------------------------------
__global__ void __launch_bounds__(256) cvt_wt_kernel(const float* __restrict__ W, int slot)
{
    __shared__ float t[32][33];
    const int n0 = blockIdx.x * 32, k0 = blockIdx.y * 32;
    const int tx = threadIdx.x & 31, ty = threadIdx.x >> 5;   // 32 x 8
    #pragma unroll
    for (int j = 0; j < 4; j++)
        t[ty + j * 8][tx] = W[(k0 + ty + j * 8) * DM + n0 + tx];
    __syncthreads();
    __nv_bfloat16* wh = g_WTh + (size_t)slot * DM * DM;
    __nv_bfloat16* wl = g_WTl + (size_t)slot * DM * DM;
    #pragma unroll
    for (int j = 0; j < 4; j++) {
        int n = n0 + ty + j * 8, k = k0 + tx;
        float v = t[tx][ty + j * 8];
        __nv_bfloat16 h = __float2bfloat16(v);
        wh[(size_t)n * DM + k] = h;
        wl[(size_t)n * DM + k] = __float2bfloat16(v - __bfloat162float(h));
    }
}

// ---------------------------------------------------------------------------
// Projection GEMM via split-bf16 HMMA.
// Tile M=64 (4 warps x 16 rows), N=64 (= one head), K-steps of 64, 12 steps.
// WHICH: 0 Q, 1 K (write [bh][s][d]), 2 V (write [bh][d][s])
// ---------------------------------------------------------------------------
#define POAH 0u
#define POAL 8192u
#define POBH 16384u
#define POBL 24576u

template<int WHICH>
__global__ void __launch_bounds__(128) proj_mma_kernel(const float* __restrict__ bias)
{
    __shared__ __align__(1024) char sm[32768];
    const unsigned sb = smem_u32(sm);
    const int tid  = threadIdx.x;
    const int lane = tid & 31;
    const int wid  = tid >> 5;
    const int h  = blockIdx.x;        // n-tile == head
    const int m0 = blockIdx.y * 64;

    const __nv_bfloat16* Xh = g_Xh + (size_t)WHICH * MK;
    const __nv_bfloat16* Xl = g_Xl + (size_t)WHICH * MK;
    const __nv_bfloat16* Bh = g_WTh + (size_t)WHICH * DM * DM;
    const __nv_bfloat16* Bl = g_WTl + (size_t)WHICH * DM * DM;

    const int aRow = lane & 15;
    const int aSel = (lane >> 4) & 1;
    const int bRow = ((lane >> 4) & 1) * 8 + (lane & 7);
    const int bSel = (lane >> 3) & 1;

    float acc[8][4];
    #pragma unroll
    for (int i = 0; i < 8; i++)
        #pragma unroll
        for (int j = 0; j < 4; j++) acc[i][j] = 0.f;

    for (int k0 = 0; k0 < DM; k0 += 64) {
        __syncthreads();
        // A tile: rows m0..m0+63, cols k0..k0+63 of [8192][768] bf16
        #pragma unroll
        for (int i = 0; i < 4; i++) {
            int c = tid + i * 128;
            int row = c >> 3, col = c & 7;
            unsigned sw = SWZ((unsigned)(row * 128 + col * 16));
            const uint4* pa = (const uint4*)(Xh + (size_t)(m0 + row) * DM + k0) + col;
            const uint4* pl = (const uint4*)(Xl + (size_t)(m0 + row) * DM + k0) + col;
            *(uint4*)(sm + POAH + sw) = *pa;
            *(uint4*)(sm + POAL + sw) = *pl;
            // B tile: rows n (h*64..+63), cols k0..k0+63 of W^T [768][768]
            const uint4* pb = (const uint4*)(Bh + (size_t)(h * 64 + row) * DM + k0) + col;
            const uint4* pc = (const uint4*)(Bl + (size_t)(h * 64 + row) * DM + k0) + col;
            *(uint4*)(sm + POBH + sw) = *pb;
            *(uint4*)(sm + POBL + sw) = *pc;
        }
        __syncthreads();

        #pragma unroll
        for (int kc = 0; kc < 4; kc++) {
            unsigned aoff = SWZ((unsigned)((wid * 16 + aRow) * 128 + kc * 32 + aSel * 16));
            unsigned ah4[4], al4[4];
            ldsm4(ah4, sb + POAH + aoff);
            ldsm4(al4, sb + POAL + aoff);
            #pragma unroll
            for (int t = 0; t < 4; t++) {
                unsigned boff = SWZ((unsigned)((t * 16 + bRow) * 128 + kc * 32 + bSel * 16));
                unsigned bh4[4], bl4[4];
                ldsm4(bh4, sb + POBH + boff);
                ldsm4(bl4, sb + POBL + boff);
                mma16816(acc[2*t],   ah4, bh4);
                mma16816(acc[2*t+1], ah4, bh4 + 2);
                mma16816(acc[2*t],   al4, bh4);
                mma16816(acc[2*t+1], al4, bh4 + 2);
                mma16816(acc[2*t],   ah4, bl4);
                mma16816(acc[2*t+1], ah4, bl4 + 2);
            }
        }
    }

    // epilogue: + bias, split hi/lo, write head layout
    __nv_bfloat16 *oh = (WHICH == 0) ? g_Qh : (WHICH == 1) ? g_Kh : g_Vh;
    __nv_bfloat16 *ol = (WHICH == 0) ? g_Ql : (WHICH == 1) ? g_Kl : g_Vl;
    const int r0 = lane >> 2, colb = (lane & 3) * 2;
    #pragma unroll
    for (int nt = 0; nt < 8; nt++) {
        int d0 = nt * 8 + colb;
        float bb0 = bias[h * 64 + d0];
        float bb1 = bias[h * 64 + d0 + 1];
        #pragma unroll
        for (int u = 0; u < 2; u++) {
            int m = m0 + wid * 16 + r0 + u * 8;
            int b = m >> 11;
            int s = m & 2047;
            int bhh = b * H_ + h;
            float v0 = acc[nt][u * 2 + 0] + bb0;
            float v1 = acc[nt][u * 2 + 1] + bb1;
            unsigned hp = packbf(v0, v1);
            unsigned lp = packbf(v0 - __int_as_float(hp << 16),
                                 v1 - __int_as_float(hp & 0xFFFF0000u));
            if (WHICH == 2) {
                size_t i0 = (size_t)(bhh * DK + d0) * S_ + s;
                size_t i1 = i0 + S_;
                oh[i0] = __ushort_as_bfloat16((unsigned short)(hp & 0xFFFF));
                oh[i1] = __ushort_as_bfloat16((unsigned short)(hp >> 16));
                ol[i0] = __ushort_as_bfloat16((unsigned short)(lp & 0xFFFF));
                ol[i1] = __ushort_as_bfloat16((unsigned short)(lp >> 16));
            } else {
                size_t i0 = (size_t)(bhh * S_ + s) * DK + d0;
                *(unsigned*)(oh + i0) = hp;
                *(unsigned*)(ol + i0) = lp;
            }
        }
    }
}

// ---------------------------------------------------------------------------
// HMMA flash attention (round-4 verified; 526us, tensor=48%)
// ---------------------------------------------------------------------------
#define OQH 0u
#define OQL 8192u
#define OKH 16384u
#define OKL 24576u
#define OVH 32768u
#define OVL 40960u
#define SMEM_BYTES 49152

__global__ void __launch_bounds__(128) attn_mma_kernel(float* __restrict__ out)
{
    extern __shared__ char sm[];
    const unsigned sb = smem_u32(sm);
    const int tid  = threadIdx.x;
    const int lane = tid & 31;
    const int wid  = tid >> 5;
    const int q0 = blockIdx.x * 64;
    const int bh = blockIdx.y;

    const int aRow = lane & 15;
    const int aSel = (lane >> 4) & 1;
    const int bRow = ((lane >> 4) & 1) * 8 + (lane & 7);
    const int bSel = (lane >> 3) & 1;
    const int qbase = wid * 16;

    {
        const uint4* qh = (const uint4*)g_Qh + (size_t)(bh * S_ + q0) * 8;
        const uint4* ql = (const uint4*)g_Ql + (size_t)(bh * S_ + q0) * 8;
        #pragma unroll
        for (int i = 0; i < 4; i++) {
            int c = tid + i * 128;
            int row = c >> 3, col = c & 7;
            unsigned sw = SWZ((unsigned)(row * 128 + col * 16));
            *(uint4*)(sm + OQH + sw) = qh[row * 8 + col];
            *(uint4*)(sm + OQL + sw) = ql[row * 8 + col];
        }
    }

    float O[8][4];
    #pragma unroll
    for (int i = 0; i < 8; i++)
        #pragma unroll
        for (int j = 0; j < 4; j++) O[i][j] = 0.f;
    float m20 = -1e30f, m21 = -1e30f, l0 = 0.f, l1 = 0.f;
    const float SC = 0.1803368801111333f;   // 0.125 * log2(e)

    for (int k0 = 0; k0 < S_; k0 += 64) {
        __syncthreads();
        {
            const uint4* kh = (const uint4*)g_Kh + (size_t)(bh * S_ + k0) * 8;
            const uint4* kl = (const uint4*)g_Kl + (size_t)(bh * S_ + k0) * 8;
            #pragma unroll
            for (int i = 0; i < 4; i++) {
                int c = tid + i * 128;
                int row = c >> 3, col = c & 7;
                unsigned sw = SWZ((unsigned)(row * 128 + col * 16));
                *(uint4*)(sm + OKH + sw) = kh[row * 8 + col];
                *(uint4*)(sm + OKL + sw) = kl[row * 8 + col];
            }
            const uint4* vh = (const uint4*)g_Vh + (size_t)(bh * DK) * 256 + k0 / 8;
            const uint4* vl = (const uint4*)g_Vl + (size_t)(bh * DK) * 256 + k0 / 8;
            #pragma unroll
            for (int i = 0; i < 4; i++) {
                int c = tid + i * 128;
                int row = c >> 3, col = c & 7;
                unsigned sw = SWZ((unsigned)(row * 128 + col * 16));
                *(uint4*)(sm + OVH + sw) = vh[row * 256 + col];
                *(uint4*)(sm + OVL + sw) = vl[row * 256 + col];
            }
        }
        __syncthreads();

        float S[8][4];
        #pragma unroll
        for (int i = 0; i < 8; i++)
            #pragma unroll
            for (int j = 0; j < 4; j++) S[i][j] = 0.f;

        #pragma unroll
        for (int c = 0; c < 4; c++) {
            unsigned qoff = SWZ((unsigned)((qbase + aRow) * 128 + c * 32 + aSel * 16));
            unsigned qh4[4], ql4[4];
            ldsm4(qh4, sb + OQH + qoff);
            ldsm4(ql4, sb + OQL + qoff);
            #pragma unroll
            for (int t = 0; t < 4; t++) {
                unsigned koff = SWZ((unsigned)((t * 16 + bRow) * 128 + c * 32 + bSel * 16));
                unsigned kh4[4], kl4[4];
                ldsm4(kh4, sb + OKH + koff);
                ldsm4(kl4, sb + OKL + koff);
                mma16816(S[2*t],   qh4, kh4);
                mma16816(S[2*t+1], qh4, kh4 + 2);
                mma16816(S[2*t],   ql4, kh4);
                mma16816(S[2*t+1], ql4, kh4 + 2);
                mma16816(S[2*t],   qh4, kl4);
                mma16816(S[2*t+1], qh4, kl4 + 2);
            }
        }

        float smax0 = -1e30f, smax1 = -1e30f;
        #pragma unroll
        for (int nt = 0; nt < 8; nt++) {
            smax0 = fmaxf(smax0, fmaxf(S[nt][0], S[nt][1]));
            smax1 = fmaxf(smax1, fmaxf(S[nt][2], S[nt][3]));
        }
        smax0 = fmaxf(smax0, __shfl_xor_sync(0xffffffffu, smax0, 1));
        smax0 = fmaxf(smax0, __shfl_xor_sync(0xffffffffu, smax0, 2));
        smax1 = fmaxf(smax1, __shfl_xor_sync(0xffffffffu, smax1, 1));
        smax1 = fmaxf(smax1, __shfl_xor_sync(0xffffffffu, smax1, 2));

        float mn0 = fmaxf(m20, smax0 * SC);
        float mn1 = fmaxf(m21, smax1 * SC);
        float al0 = exp2fast(m20 - mn0);
        float al1 = exp2fast(m21 - mn1);
        m20 = mn0; m21 = mn1;
        #pragma unroll
        for (int nt = 0; nt < 8; nt++) {
            O[nt][0] *= al0; O[nt][1] *= al0;
            O[nt][2] *= al1; O[nt][3] *= al1;
        }

        unsigned ph[4][4], pl[4][4];
        float rs0 = 0.f, rs1 = 0.f;
        #pragma unroll
        for (int t = 0; t < 4; t++) {
            #pragma unroll
            for (int u = 0; u < 2; u++) {
                float* s4 = S[2*t + u];
                float p0 = exp2fast(fmaf(s4[0], SC, -mn0));
                float p1 = exp2fast(fmaf(s4[1], SC, -mn0));
                float p2 = exp2fast(fmaf(s4[2], SC, -mn1));
                float p3 = exp2fast(fmaf(s4[3], SC, -mn1));
                rs0 += p0 + p1;
                rs1 += p2 + p3;
                unsigned h01 = packbf(p0, p1);
                unsigned h23 = packbf(p2, p3);
                float q0f = __int_as_float(h01 << 16);
                float q1f = __int_as_float(h01 & 0xFFFF0000u);
                float q2f = __int_as_float(h23 << 16);
                float q3f = __int_as_float(h23 & 0xFFFF0000u);
                ph[t][u*2]   = h01;
                ph[t][u*2+1] = h23;
                pl[t][u*2]   = packbf(p0 - q0f, p1 - q1f);
                pl[t][u*2+1] = packbf(p2 - q2f, p3 - q3f);
            }
        }
        rs0 += __shfl_xor_sync(0xffffffffu, rs0, 1);
        rs0 += __shfl_xor_sync(0xffffffffu, rs0, 2);
        rs1 += __shfl_xor_sync(0xffffffffu, rs1, 1);
        rs1 += __shfl_xor_sync(0xffffffffu, rs1, 2);
        l0 = l0 * al0 + rs0;
        l1 = l1 * al1 + rs1;

        #pragma unroll
        for (int kc = 0; kc < 4; kc++) {
            #pragma unroll
            for (int du = 0; du < 4; du++) {
                unsigned voff = SWZ((unsigned)((du * 16 + bRow) * 128 + kc * 32 + bSel * 16));
                unsigned vh4[4], vl4[4];
                ldsm4(vh4, sb + OVH + voff);
                ldsm4(vl4, sb + OVL + voff);
                mma16816(O[2*du],   ph[kc], vh4);
                mma16816(O[2*du+1], ph[kc], vh4 + 2);
                mma16816(O[2*du],   pl[kc], vh4);
                mma16816(O[2*du+1], pl[kc], vh4 + 2);
                mma16816(O[2*du],   ph[kc], vl4);
                mma16816(O[2*du+1], ph[kc], vl4 + 2);
            }
        }
    }

    {
        float inv0 = 1.0f / l0, inv1 = 1.0f / l1;
        int b = bh / H_, h = bh % H_;
        int r0 = lane >> 2;
        int colb = (lane & 3) * 2;
        float* base0 = out + (size_t)(b * S_ + q0 + qbase + r0) * DM + h * DK;
        float* base1 = base0 + 8 * DM;
        #pragma unroll
        for (int nt = 0; nt < 8; nt++) {
            float2 v0 = make_float2(O[nt][0] * inv0, O[nt][1] * inv0);
            float2 v1 = make_float2(O[nt][2] * inv1, O[nt][3] * inv1);
            *(float2*)(base0 + nt * 8 + colb) = v0;
            *(float2*)(base1 + nt * 8 + colb) = v1;
        }
    }
}

// ---------------------------------------------------------------------------
extern "C" void kernel_launch(void* const* d_in, const int* in_sizes, int n_in,
                              void* d_out, int out_size)
{
    const float* q   = (const float*)d_in[0];
    const float* k   = (const float*)d_in[1];
    const float* v   = (const float*)d_in[2];
    const float* W_Q = (const float*)d_in[3];
    const float* b_Q = (const float*)d_in[4];
    const float* W_K = (const float*)d_in[5];
    const float* b_K = (const float*)d_in[6];
    const float* W_V = (const float*)d_in[7];
    const float* b_V = (const float*)d_in[8];
    float* out = (float*)d_out;

    cudaFuncSetAttribute(attn_mma_kernel, cudaFuncAttributeMaxDynamicSharedMemorySize, SMEM_BYTES);

    // prepass: convert inputs and transpose weights to bf16 hi/lo
    cvt_x_kernel<<<MK / 4 / 256, 256>>>(q, 0);
    cvt_x_kernel<<<MK / 4 / 256, 256>>>(k, 1);
    cvt_x_kernel<<<MK / 4 / 256, 256>>>(v, 2);
    dim3 wg(DM / 32, DM / 32);
    cvt_wt_kernel<<<wg, 256>>>(W_Q, 0);
    cvt_wt_kernel<<<wg, 256>>>(W_K, 1);
    cvt_wt_kernel<<<wg, 256>>>(W_V, 2);

    // projections (HMMA)
    dim3 pgrid(H_, (B_ * S_) / 64);        // (12, 128)
    proj_mma_kernel<0><<<pgrid, 128>>>(b_Q);
    proj_mma_kernel<1><<<pgrid, 128>>>(b_K);
    proj_mma_kernel<2><<<pgrid, 128>>>(b_V);

    // attention (HMMA)
    dim3 agrid(S_ / 64, BH);               // (32, 48)
    attn_mma_kernel<<<agrid, 128, SMEM_BYTES>>>(out);
}